// round 7
// baseline (speedup 1.0000x reference)
#include <cuda_runtime.h>
#include <cuda_bf16.h>
#include <cstdint>

#define BB    8192
#define CC    1024
#define NCLS  100
#define CAP   1024
#define NTP   3          // block pairs (0,0),(0,1),(1,1): class size <= 256
#define NCTA  (NCLS * NTP)
#define TINV  0.25f      // 1/T, T=4
#define KC    64         // bf16 per K-chunk (128 bytes/row)
#define NCHUNK (CC / KC) // 16
#define NSTG  4          // cp.async pipeline stages

// ---- scratch (device globals: no allocations allowed) ----
__device__ __nv_bfloat16 g_pb[(size_t)BB * CC];   // 16 MB bf16 probs
__device__ float g_t[BB];
__device__ int   g_cnt[NCLS];
__device__ int   g_list[NCLS * CAP];
__device__ float g_partial[NCTA];
__device__ int   g_done = 0;                      // reset by last CTA each run

// ---- helpers ----
__device__ __forceinline__ uint32_t smem_u32(const void* p) {
  uint32_t a;
  asm("{ .reg .u64 t; cvta.to.shared.u64 t, %1; cvt.u32.u64 %0, t; }" : "=r"(a) : "l"(p));
  return a;
}
__device__ __forceinline__ void cpa16(uint32_t smem_dst, const void* gsrc) {
  asm volatile("cp.async.cg.shared.global [%0], [%1], 16;" :: "r"(smem_dst), "l"(gsrc));
}
__device__ __forceinline__ void cp_commit() { asm volatile("cp.async.commit_group;"); }
template <int N> __device__ __forceinline__ void cp_wait() {
  asm volatile("cp.async.wait_group %0;" :: "n"(N));
}
__device__ __forceinline__ uint32_t swz(uint32_t b) { return b ^ ((b >> 3) & 0x70); }

__device__ __forceinline__ void ldsm_x4(uint32_t a, uint32_t& r0, uint32_t& r1,
                                        uint32_t& r2, uint32_t& r3) {
  asm volatile("ldmatrix.sync.aligned.m8n8.x4.shared.b16 {%0,%1,%2,%3}, [%4];"
               : "=r"(r0), "=r"(r1), "=r"(r2), "=r"(r3) : "r"(a));
}
__device__ __forceinline__ void mma16816(float* c, uint32_t a0, uint32_t a1,
                                         uint32_t a2, uint32_t a3,
                                         uint32_t b0, uint32_t b1) {
  asm volatile(
      "mma.sync.aligned.m16n8k16.row.col.f32.bf16.bf16.f32 "
      "{%0,%1,%2,%3}, {%4,%5,%6,%7}, {%8,%9}, {%0,%1,%2,%3};"
      : "+f"(c[0]), "+f"(c[1]), "+f"(c[2]), "+f"(c[3])
      : "r"(a0), "r"(a1), "r"(a2), "r"(a3), "r"(b0), "r"(b1));
}

__device__ __forceinline__ float warpMaxf(float v) {
#pragma unroll
  for (int o = 16; o > 0; o >>= 1) v = fmaxf(v, __shfl_xor_sync(0xffffffffu, v, o));
  return v;
}
__device__ __forceinline__ float warpSumf(float v) {
#pragma unroll
  for (int o = 16; o > 0; o >>= 1) v += __shfl_xor_sync(0xffffffffu, v, o);
  return v;
}

// exp(z) for z <= 0 via 2^w with degree-7 poly: FMA pipe only, avoids MUFU.EX2.
__device__ __forceinline__ float fast_exp(float z) {
  float w  = z * 1.4426950408889634f;
  float nf = floorf(w);
  float f  = w - nf;
  float r  = 1.5252733e-5f;
  r = fmaf(r, f, 1.5403530e-4f);
  r = fmaf(r, f, 1.3333558e-3f);
  r = fmaf(r, f, 9.6181291e-3f);
  r = fmaf(r, f, 5.5504109e-2f);
  r = fmaf(r, f, 2.4022651e-1f);
  r = fmaf(r, f, 6.9314718e-1f);
  r = fmaf(r, f, 1.0f);
  return r * __int_as_float(((int)nf + 127) << 23);
}

// ---- setup (runs inside softmax CTA 0): dtype probe + class scatter ----
// JAX with x64 disabled silently stores int64-requested targets as int32.
// True LE int64 in [0,100) => every odd 32-bit word of the first BB words is 0.
__device__ __forceinline__ void do_setup(const int* __restrict__ tgt32, int tid) {
  __shared__ int scnt[NCLS];
  __shared__ int nz;
  for (int i = tid; i < NCLS; i += 256) scnt[i] = 0;
  if (tid == 0) nz = 0;
  __syncthreads();

  int c = 0;
  for (int i = tid; i < BB / 2; i += 256)
    if (tgt32[2 * i + 1] != 0) c++;
  if (c) atomicAdd(&nz, 1);
  __syncthreads();
  int stride = (nz == 0) ? 2 : 1;   // 2 => int64 low words

  for (int i = tid; i < BB; i += 256) {
    int cl = tgt32[(size_t)i * stride];
    if ((unsigned)cl < NCLS) {
      int s = atomicAdd(&scnt[cl], 1);
      if (s < CAP) g_list[cl * CAP + s] = i;
    }
  }
  __syncthreads();
  for (int i = tid; i < NCLS; i += 256) g_cnt[i] = scnt[i];
}

// ---------------- softmax + t (warp per row) + embedded setup in CTA 0 ----------------
__global__ void __launch_bounds__(256) softmax_kernel(const float* __restrict__ x,
                                                      const int* __restrict__ tgt32) {
  if (blockIdx.x == 0) do_setup(tgt32, threadIdx.x);

  int wid = threadIdx.x >> 5, lid = threadIdx.x & 31;
  int row = blockIdx.x * 8 + wid;

  const float4* src = reinterpret_cast<const float4*>(x + (size_t)row * CC);
  float y[32];
  float m = -3.4e38f;
#pragma unroll
  for (int q = 0; q < 8; q++) {
    float4 v = src[q * 32 + lid];
    y[4 * q + 0] = v.x * TINV; y[4 * q + 1] = v.y * TINV;
    y[4 * q + 2] = v.z * TINV; y[4 * q + 3] = v.w * TINV;
    m = fmaxf(m, fmaxf(fmaxf(y[4 * q], y[4 * q + 1]), fmaxf(y[4 * q + 2], y[4 * q + 3])));
  }
  m = warpMaxf(m);

  float e[32];
  float s = 0.0f;
#pragma unroll
  for (int i = 0; i < 32; i++) { e[i] = fast_exp(y[i] - m); s += e[i]; }
  s = warpSumf(s);
  float invS = 1.0f / s;
  float lnS  = __logf(s);

  uint2* dst = reinterpret_cast<uint2*>(g_pb + (size_t)row * CC);
  float tl = 0.0f;
#pragma unroll
  for (int q = 0; q < 8; q++) {
    float p0 = fmaf(e[4 * q + 0], invS, 1e-8f);
    float p1 = fmaf(e[4 * q + 1], invS, 1e-8f);
    float p2 = fmaf(e[4 * q + 2], invS, 1e-8f);
    float p3 = fmaf(e[4 * q + 3], invS, 1e-8f);
    // log p ~= y - m - lnS (+1e-8 shift perturbs log by ~1e-5 abs -> negligible)
    tl += p0 * (y[4 * q + 0] - m - lnS) + p1 * (y[4 * q + 1] - m - lnS)
        + p2 * (y[4 * q + 2] - m - lnS) + p3 * (y[4 * q + 3] - m - lnS);
    __nv_bfloat162 h01 = __floats2bfloat162_rn(p0, p1);
    __nv_bfloat162 h23 = __floats2bfloat162_rn(p2, p3);
    uint2 pk;
    pk.x = *reinterpret_cast<uint32_t*>(&h01);
    pk.y = *reinterpret_cast<uint32_t*>(&h23);
    dst[q * 32 + lid] = pk;
  }
  tl = warpSumf(tl);
  if (lid == 0) g_t[row] = tl * (1.0f / CC);
}

// ---------------- per-class Gram via warp-level bf16 HMMA + fused final reduce ------
// One CTA per (class, 128-block pair). 8 warps; warp w owns rows [w*16, w*16+16).
// 4-stage cp.async pipeline (3-chunk / 48KB prefetch), one __syncthreads per chunk.
// Last CTA to finish reduces g_partial into d_out (deterministic fixed-order sum).
__global__ void __launch_bounds__(256) gram_kernel(float* __restrict__ out) {
  int c = blockIdx.y, tp = blockIdx.x;
  int g = g_cnt[c];
  if (g > 256) g = 256;
  int bi = (tp == 2) ? 1 : 0;
  int bj = (tp == 0) ? 0 : 1;
  int gA = min(g - bi * 128, 128);
  int gB = min(g - bj * 128, 128);
  bool diag = (bi == bj);
  bool active = (g >= 2) && (gA > 0) && (gB > 0);

  __shared__ __align__(1024) __nv_bfloat16 sT[NSTG][128 * KC];  // 4 x 16 KB
  __shared__ int   sRA[128], sRB[128];
  __shared__ float sTA[128], sTB[128];
  __shared__ float rs[8];
  __shared__ int   sLast;

  int tid = threadIdx.x, wid = tid >> 5, lid = tid & 31;
  float total = 0.0f;

  if (active) {
    if (tid < 128) {
      int r = g_list[c * CAP + min(bi * 128 + tid, g - 1)];
      sRA[tid] = r; sTA[tid] = g_t[r];
    } else {
      int t2 = tid - 128;
      int r = g_list[c * CAP + min(bj * 128 + t2, g - 1)];
      sRB[t2] = r; sTB[t2] = g_t[r];
    }
    __syncthreads();

    // fixed per-thread load slots: 4 x (row, 16B granule) per tile
    const __nv_bfloat16* srcA[4];
    const __nv_bfloat16* srcB[4];
    uint32_t soff[4];
#pragma unroll
    for (int q = 0; q < 4; q++) {
      int s = tid + 256 * q;
      int row = s >> 3, gr = s & 7;
      srcA[q] = g_pb + (size_t)sRA[row] * CC + gr * 8;
      srcB[q] = g_pb + (size_t)sRB[row] * CC + gr * 8;
      soff[q] = swz((uint32_t)(row * 128 + gr * 16));
    }

    uint32_t stu[NSTG];
#pragma unroll
    for (int s = 0; s < NSTG; s++) stu[s] = smem_u32(&sT[s][0]);

    float acc[16][4];
#pragma unroll
    for (int i = 0; i < 16; i++)
#pragma unroll
      for (int j = 0; j < 4; j++) acc[i][j] = 0.0f;

    int  m0    = wid * 16;
    bool act   = (m0 < gA);
    int  nPair = (gB + 15) >> 4;   // 16-col tile pairs actually needed
    uint32_t rowAb = (uint32_t)((m0 + (lid & 15)) * 128 + (lid >> 4) * 16);
    uint32_t rowBb = (uint32_t)(((lid & 7) + ((lid >> 4) << 3)) * 128 + ((lid >> 3) & 1) * 16);

    auto compute = [&](uint32_t aB, uint32_t bB) {
      if (!act) return;
#pragma unroll
      for (int kk = 0; kk < 4; kk++) {        // 4 k16 steps per 64-chunk
        uint32_t a0, a1, a2, a3;
        ldsm_x4(aB + swz(rowAb + kk * 32), a0, a1, a2, a3);
#pragma unroll
        for (int nt2 = 0; nt2 < 8; nt2++) {
          if (nt2 < nPair) {
            uint32_t b0, b1, b2, b3;
            ldsm_x4(bB + swz(rowBb + nt2 * 2048 + kk * 32), b0, b1, b2, b3);
            mma16816(acc[2 * nt2],     a0, a1, a2, a3, b0, b1);
            mma16816(acc[2 * nt2 + 1], a0, a1, a2, a3, b2, b3);
          }
        }
      }
    };

    if (diag) {
      // D = A.A^T: 4-stage pipeline, 3-chunk prefetch, 1 sync/chunk.
#pragma unroll
      for (int s = 0; s < NSTG - 1; s++) {
        int off = s * KC;
#pragma unroll
        for (int q = 0; q < 4; q++) cpa16(stu[s] + soff[q], srcA[q] + off);
        cp_commit();
      }
      for (int ch = 0; ch < NCHUNK; ch++) {
        cp_wait<NSTG - 2>();        // oldest pending group (chunk ch) complete
        __syncthreads();            // also: stage (ch+3)&3 consumed by all (ch-1 done)
        int pre = ch + NSTG - 1;
        if (pre < NCHUNK) {
          int off = pre * KC;
          uint32_t nxt = stu[pre & (NSTG - 1)];
#pragma unroll
          for (int q = 0; q < 4; q++) cpa16(nxt + soff[q], srcA[q] + off);
        }
        cp_commit();                // always commit: keeps group counting uniform
        uint32_t cur = stu[ch & (NSTG - 1)];
        compute(cur, cur);
      }
    } else {
      // off-diagonal (class > 128 rows; rare): A/B serial in stages 0/1
      for (int ch = 0; ch < NCHUNK; ch++) {
        int off = ch * KC;
#pragma unroll
        for (int q = 0; q < 4; q++) cpa16(stu[0] + soff[q], srcA[q] + off);
#pragma unroll
        for (int q = 0; q < 4; q++) cpa16(stu[1] + soff[q], srcB[q] + off);
        cp_commit();
        cp_wait<0>();
        __syncthreads();
        compute(stu[0], stu[1]);
        __syncthreads();
      }
    }

    // epilogue: acc[nt] C-fragment: c0=(r0,n0), c1=(r0,n0+1), c2=(r1,n0), c3=(r1,n0+1)
    float local = 0.0f;
    if (act) {
      float inv = 1.0f / (float)CC;
      int gid = lid >> 2, tg = lid & 3;
      int r0 = m0 + gid, r1 = r0 + 8;
      float tA0 = sTA[r0], tA1 = sTA[r1];
      bool v0 = r0 < gA, v1 = r1 < gA;
#pragma unroll
      for (int nt = 0; nt < 16; nt++) {
        int n0 = nt * 8 + tg * 2;
#pragma unroll
        for (int e2 = 0; e2 < 4; e2++) {
          int  rr = (e2 & 2) ? r1 : r0;
          bool vr = (e2 & 2) ? v1 : v0;
          int  cl = n0 + (e2 & 1);
          if (vr && (cl < gB) && (!diag || rr != cl)) {
            float cross = acc[nt][e2] * inv;
            float d = sTB[cl] - cross;          // kl[row, col]
            local += d * d;
            if (!diag) {                        // also ordered pair (col, row)
              float d2 = ((e2 & 2) ? tA1 : tA0) - cross;
              local += d2 * d2;
            }
          }
        }
      }
    }
    local = warpSumf(local);
    if (lid == 0) rs[wid] = local;
    __syncthreads();
    if (tid == 0) {
#pragma unroll
      for (int w = 0; w < 8; w++) total += rs[w];
    }
  }

  // ---- publish partial, then last-CTA-done final reduce ----
  if (tid == 0) {
    g_partial[c * NTP + tp] = total;
    __threadfence();
    int old = atomicAdd(&g_done, 1);
    sLast = (old == NCTA - 1) ? 1 : 0;
  }
  __syncthreads();
  if (sLast) {
    float s = 0.0f;
    for (int i = tid; i < NCTA; i += 256) s += g_partial[i];
    s = warpSumf(s);
    if (lid == 0) rs[wid] = s;
    __syncthreads();
    if (tid == 0) {
      float tot = 0.0f;
#pragma unroll
      for (int w = 0; w < 8; w++) tot += rs[w];
      out[0] = tot / (float)BB;
      g_done = 0;             // reset for next graph replay
    }
  }
}

extern "C" void kernel_launch(void* const* d_in, const int* in_sizes, int n_in,
                              void* d_out, int out_size) {
  const float* x;
  const int* tgt32;
  if (in_sizes[0] == BB) {       // defensive input-order detection
    tgt32 = (const int*)d_in[0];
    x     = (const float*)d_in[1];
  } else {
    x     = (const float*)d_in[0];
    tgt32 = (const int*)d_in[1];
  }

  softmax_kernel<<<BB / 8, 256>>>(x, tgt32);
  dim3 gg(NTP, NCLS);
  gram_kernel<<<gg, 256>>>((float*)d_out);
}

// round 8
// speedup vs baseline: 1.0487x; 1.0487x over previous
#include <cuda_runtime.h>
#include <cuda_bf16.h>
#include <cstdint>

#define BB    8192
#define CC    1024
#define NCLS  100
#define CAP   1024
#define NTP   3          // block pairs (0,0),(0,1),(1,1): class size <= 256
#define NBX   (NTP * 2)  // x-dim: tile-pair * N-half
#define NCTA  (NCLS * NBX)
#define TINV  0.25f      // 1/T, T=4
#define KC    64         // bf16 per K-chunk (128 bytes/row)
#define NCHUNK (CC / KC) // 16
#define NSTG  4          // cp.async pipeline stages

// ---- scratch (device globals: no allocations allowed) ----
__device__ __nv_bfloat16 g_pb[(size_t)BB * CC];   // 16 MB bf16 probs
__device__ float g_t[BB];
__device__ int   g_cnt[NCLS];
__device__ int   g_list[NCLS * CAP];
__device__ float g_partial[NCTA];
__device__ int   g_done = 0;                      // reset by last CTA each run

// ---- helpers ----
__device__ __forceinline__ uint32_t smem_u32(const void* p) {
  uint32_t a;
  asm("{ .reg .u64 t; cvta.to.shared.u64 t, %1; cvt.u32.u64 %0, t; }" : "=r"(a) : "l"(p));
  return a;
}
__device__ __forceinline__ void cpa16(uint32_t smem_dst, const void* gsrc) {
  asm volatile("cp.async.cg.shared.global [%0], [%1], 16;" :: "r"(smem_dst), "l"(gsrc));
}
__device__ __forceinline__ void cp_commit() { asm volatile("cp.async.commit_group;"); }
template <int N> __device__ __forceinline__ void cp_wait() {
  asm volatile("cp.async.wait_group %0;" :: "n"(N));
}
__device__ __forceinline__ uint32_t swz(uint32_t b) { return b ^ ((b >> 3) & 0x70); }

__device__ __forceinline__ void ldsm_x4(uint32_t a, uint32_t& r0, uint32_t& r1,
                                        uint32_t& r2, uint32_t& r3) {
  asm volatile("ldmatrix.sync.aligned.m8n8.x4.shared.b16 {%0,%1,%2,%3}, [%4];"
               : "=r"(r0), "=r"(r1), "=r"(r2), "=r"(r3) : "r"(a));
}
__device__ __forceinline__ void mma16816(float* c, uint32_t a0, uint32_t a1,
                                         uint32_t a2, uint32_t a3,
                                         uint32_t b0, uint32_t b1) {
  asm volatile(
      "mma.sync.aligned.m16n8k16.row.col.f32.bf16.bf16.f32 "
      "{%0,%1,%2,%3}, {%4,%5,%6,%7}, {%8,%9}, {%0,%1,%2,%3};"
      : "+f"(c[0]), "+f"(c[1]), "+f"(c[2]), "+f"(c[3])
      : "r"(a0), "r"(a1), "r"(a2), "r"(a3), "r"(b0), "r"(b1));
}

__device__ __forceinline__ float warpMaxf(float v) {
#pragma unroll
  for (int o = 16; o > 0; o >>= 1) v = fmaxf(v, __shfl_xor_sync(0xffffffffu, v, o));
  return v;
}
__device__ __forceinline__ float warpSumf(float v) {
#pragma unroll
  for (int o = 16; o > 0; o >>= 1) v += __shfl_xor_sync(0xffffffffu, v, o);
  return v;
}

// exp(z) for z <= 0 via 2^w with degree-7 poly: FMA pipe only, avoids MUFU.EX2.
__device__ __forceinline__ float fast_exp(float z) {
  float w  = z * 1.4426950408889634f;
  float nf = floorf(w);
  float f  = w - nf;
  float r  = 1.5252733e-5f;
  r = fmaf(r, f, 1.5403530e-4f);
  r = fmaf(r, f, 1.3333558e-3f);
  r = fmaf(r, f, 9.6181291e-3f);
  r = fmaf(r, f, 5.5504109e-2f);
  r = fmaf(r, f, 2.4022651e-1f);
  r = fmaf(r, f, 6.9314718e-1f);
  r = fmaf(r, f, 1.0f);
  return r * __int_as_float(((int)nf + 127) << 23);
}

// ---- setup (runs inside softmax CTA 0): dtype probe + class scatter ----
// JAX with x64 disabled silently stores int64-requested targets as int32.
// True LE int64 in [0,100) => every odd 32-bit word of the first BB words is 0.
__device__ __forceinline__ void do_setup(const int* __restrict__ tgt32, int tid) {
  __shared__ int scnt[NCLS];
  __shared__ int nz;
  for (int i = tid; i < NCLS; i += 256) scnt[i] = 0;
  if (tid == 0) nz = 0;
  __syncthreads();

  int c = 0;
  for (int i = tid; i < BB / 2; i += 256)
    if (tgt32[2 * i + 1] != 0) c++;
  if (c) atomicAdd(&nz, 1);
  __syncthreads();
  int stride = (nz == 0) ? 2 : 1;   // 2 => int64 low words

  for (int i = tid; i < BB; i += 256) {
    int cl = tgt32[(size_t)i * stride];
    if ((unsigned)cl < NCLS) {
      int s = atomicAdd(&scnt[cl], 1);
      if (s < CAP) g_list[cl * CAP + s] = i;
    }
  }
  __syncthreads();
  for (int i = tid; i < NCLS; i += 256) g_cnt[i] = scnt[i];
}

// ---------------- softmax + t (warp per row) + embedded setup in CTA 0 ----------------
__global__ void __launch_bounds__(256) softmax_kernel(const float* __restrict__ x,
                                                      const int* __restrict__ tgt32) {
  if (blockIdx.x == 0) do_setup(tgt32, threadIdx.x);

  int wid = threadIdx.x >> 5, lid = threadIdx.x & 31;
  int row = blockIdx.x * 8 + wid;

  const float4* src = reinterpret_cast<const float4*>(x + (size_t)row * CC);
  float y[32];
  float m = -3.4e38f;
#pragma unroll
  for (int q = 0; q < 8; q++) {
    float4 v = src[q * 32 + lid];
    y[4 * q + 0] = v.x * TINV; y[4 * q + 1] = v.y * TINV;
    y[4 * q + 2] = v.z * TINV; y[4 * q + 3] = v.w * TINV;
    m = fmaxf(m, fmaxf(fmaxf(y[4 * q], y[4 * q + 1]), fmaxf(y[4 * q + 2], y[4 * q + 3])));
  }
  m = warpMaxf(m);

  float e[32];
  float s = 0.0f;
#pragma unroll
  for (int i = 0; i < 32; i++) { e[i] = fast_exp(y[i] - m); s += e[i]; }
  s = warpSumf(s);
  float invS = 1.0f / s;
  float lnS  = __logf(s);

  uint2* dst = reinterpret_cast<uint2*>(g_pb + (size_t)row * CC);
  float tl = 0.0f;
#pragma unroll
  for (int q = 0; q < 8; q++) {
    float p0 = fmaf(e[4 * q + 0], invS, 1e-8f);
    float p1 = fmaf(e[4 * q + 1], invS, 1e-8f);
    float p2 = fmaf(e[4 * q + 2], invS, 1e-8f);
    float p3 = fmaf(e[4 * q + 3], invS, 1e-8f);
    // log p ~= y - m - lnS (+1e-8 shift perturbs log by ~1e-5 abs -> negligible)
    tl += p0 * (y[4 * q + 0] - m - lnS) + p1 * (y[4 * q + 1] - m - lnS)
        + p2 * (y[4 * q + 2] - m - lnS) + p3 * (y[4 * q + 3] - m - lnS);
    __nv_bfloat162 h01 = __floats2bfloat162_rn(p0, p1);
    __nv_bfloat162 h23 = __floats2bfloat162_rn(p2, p3);
    uint2 pk;
    pk.x = *reinterpret_cast<uint32_t*>(&h01);
    pk.y = *reinterpret_cast<uint32_t*>(&h23);
    dst[q * 32 + lid] = pk;
  }
  tl = warpSumf(tl);
  if (lid == 0) g_t[row] = tl * (1.0f / CC);
}

// ---------------- per-class Gram via warp-level bf16 HMMA + fused final reduce ------
// Grid (6, NCLS): x = tile-pair (3) * N-half (2). Each CTA computes a 128x64 half
// of the pair's D block: halves the per-warp HMMA chain and acc registers, and
// doubles active CTAs (200) so SMs co-host 2 CTAs (16 warps) to hide LDSM/HMMA
// latency. For the diag pair, B fragments read from the same A smem tile.
// Last CTA to finish reduces g_partial into d_out (deterministic fixed-order sum).
__global__ void __launch_bounds__(256, 2) gram_kernel(float* __restrict__ out) {
  int c  = blockIdx.y;
  int bx = blockIdx.x;            // 0..5
  int tp = bx >> 1, nh = bx & 1;  // tile pair, N-half
  int g = g_cnt[c];
  if (g > 256) g = 256;
  int bi = (tp == 2) ? 1 : 0;
  int bj = (tp == 0) ? 0 : 1;
  int gA  = min(g - bi * 128, 128);
  int gB  = min(g - bj * 128, 128);
  int gBh = gB - nh * 64;                 // valid cols in this half
  bool diag = (bi == bj);
  bool active = (g >= 2) && (gA > 0) && (gBh > 0);

  __shared__ __align__(1024) __nv_bfloat16 sT[NSTG][128 * KC];  // 4 x 16 KB
  __shared__ int   sRA[128], sRB[128];
  __shared__ float sTA[128], sTB[128];
  __shared__ float rs[8];
  __shared__ int   sLast;

  int tid = threadIdx.x, wid = tid >> 5, lid = tid & 31;
  float total = 0.0f;

  if (active) {
    if (tid < 128) {
      int r = g_list[c * CAP + min(bi * 128 + tid, g - 1)];
      sRA[tid] = r; sTA[tid] = g_t[r];
    } else {
      int t2 = tid - 128;
      int r = g_list[c * CAP + min(bj * 128 + t2, g - 1)];
      sRB[t2] = r; sTB[t2] = g_t[r];
    }
    __syncthreads();

    // fixed per-thread load slots: 4 x (row, 16B granule) per tile
    const __nv_bfloat16* srcA[4];
    const __nv_bfloat16* srcB[4];
    uint32_t soff[4];
#pragma unroll
    for (int q = 0; q < 4; q++) {
      int s = tid + 256 * q;
      int row = s >> 3, gr = s & 7;
      srcA[q] = g_pb + (size_t)sRA[row] * CC + gr * 8;
      srcB[q] = g_pb + (size_t)sRB[row] * CC + gr * 8;
      soff[q] = swz((uint32_t)(row * 128 + gr * 16));
    }

    uint32_t stu[NSTG];
#pragma unroll
    for (int s = 0; s < NSTG; s++) stu[s] = smem_u32(&sT[s][0]);

    float acc[8][4];                      // 128 rows x 64 cols half
#pragma unroll
    for (int i = 0; i < 8; i++)
#pragma unroll
      for (int j = 0; j < 4; j++) acc[i][j] = 0.0f;

    int  m0     = wid * 16;
    bool act    = (m0 < gA);
    int  nPairH = min((gBh + 15) >> 4, 4);   // 16-col groups in this half
    uint32_t rowAb = (uint32_t)((m0 + (lid & 15)) * 128 + (lid >> 4) * 16);
    uint32_t rowBb = (uint32_t)(((lid & 7) + ((lid >> 4) << 3)) * 128
                                + ((lid >> 3) & 1) * 16 + nh * 64 * 128);

    auto compute = [&](uint32_t aB, uint32_t bB) {
      if (!act) return;
#pragma unroll
      for (int kk = 0; kk < 4; kk++) {        // 4 k16 steps per 64-chunk
        uint32_t a0, a1, a2, a3;
        ldsm_x4(aB + swz(rowAb + kk * 32), a0, a1, a2, a3);
        uint32_t b[4][4];
#pragma unroll
        for (int nt2 = 0; nt2 < 4; nt2++)     // batch LDSMs: independent issue
          if (nt2 < nPairH)
            ldsm_x4(bB + swz(rowBb + nt2 * 2048 + kk * 32),
                    b[nt2][0], b[nt2][1], b[nt2][2], b[nt2][3]);
#pragma unroll
        for (int nt2 = 0; nt2 < 4; nt2++) {
          if (nt2 < nPairH) {
            mma16816(acc[2 * nt2],     a0, a1, a2, a3, b[nt2][0], b[nt2][1]);
            mma16816(acc[2 * nt2 + 1], a0, a1, a2, a3, b[nt2][2], b[nt2][3]);
          }
        }
      }
    };

    if (diag) {
      // D = A.A^T: 4-stage pipeline, 3-chunk prefetch, 1 sync/chunk.
#pragma unroll
      for (int s = 0; s < NSTG - 1; s++) {
        int off = s * KC;
#pragma unroll
        for (int q = 0; q < 4; q++) cpa16(stu[s] + soff[q], srcA[q] + off);
        cp_commit();
      }
      for (int ch = 0; ch < NCHUNK; ch++) {
        cp_wait<NSTG - 2>();        // oldest pending group (chunk ch) complete
        __syncthreads();            // also: stage (ch+3)&3 consumed by all (ch-1 done)
        int pre = ch + NSTG - 1;
        if (pre < NCHUNK) {
          int off = pre * KC;
          uint32_t nxt = stu[pre & (NSTG - 1)];
#pragma unroll
          for (int q = 0; q < 4; q++) cpa16(nxt + soff[q], srcA[q] + off);
        }
        cp_commit();                // always commit: keeps group counting uniform
        uint32_t cur = stu[ch & (NSTG - 1)];
        compute(cur, cur);          // B fragments come from the same A tile
      }
    } else {
      // off-diagonal (class > 128 rows; rare): A/B serial in stages 0/1
      for (int ch = 0; ch < NCHUNK; ch++) {
        int off = ch * KC;
#pragma unroll
        for (int q = 0; q < 4; q++) cpa16(stu[0] + soff[q], srcA[q] + off);
#pragma unroll
        for (int q = 0; q < 4; q++) cpa16(stu[1] + soff[q], srcB[q] + off);
        cp_commit();
        cp_wait<0>();
        __syncthreads();
        compute(stu[0], stu[1]);
        __syncthreads();
      }
    }

    // epilogue: acc[nt] C-fragment: c0=(r0,n0), c1=(r0,n0+1), c2=(r1,n0), c3=(r1,n0+1)
    float local = 0.0f;
    if (act) {
      float inv = 1.0f / (float)CC;
      int gid = lid >> 2, tg = lid & 3;
      int r0 = m0 + gid, r1 = r0 + 8;
      float tA0 = sTA[r0], tA1 = sTA[r1];
      bool v0 = r0 < gA, v1 = r1 < gA;
#pragma unroll
      for (int nt = 0; nt < 8; nt++) {
        int n0 = nh * 64 + nt * 8 + tg * 2;
#pragma unroll
        for (int e2 = 0; e2 < 4; e2++) {
          int  rr = (e2 & 2) ? r1 : r0;
          bool vr = (e2 & 2) ? v1 : v0;
          int  cl = n0 + (e2 & 1);
          if (vr && (cl < gB) && (!diag || rr != cl)) {
            float cross = acc[nt][e2] * inv;
            float d = sTB[cl] - cross;          // kl[row, col]
            local += d * d;
            if (!diag) {                        // also ordered pair (col, row)
              float d2 = ((e2 & 2) ? tA1 : tA0) - cross;
              local += d2 * d2;
            }
          }
        }
      }
    }
    local = warpSumf(local);
    if (lid == 0) rs[wid] = local;
    __syncthreads();
    if (tid == 0) {
#pragma unroll
      for (int w = 0; w < 8; w++) total += rs[w];
    }
  }

  // ---- publish partial, then last-CTA-done final reduce ----
  if (tid == 0) {
    g_partial[c * NBX + bx] = total;
    __threadfence();
    int old = atomicAdd(&g_done, 1);
    sLast = (old == NCTA - 1) ? 1 : 0;
  }
  __syncthreads();
  if (sLast) {
    float s = 0.0f;
    for (int i = tid; i < NCTA; i += 256) s += g_partial[i];
    s = warpSumf(s);
    if (lid == 0) rs[wid] = s;
    __syncthreads();
    if (tid == 0) {
      float tot = 0.0f;
#pragma unroll
      for (int w = 0; w < 8; w++) tot += rs[w];
      out[0] = tot / (float)BB;
      g_done = 0;             // reset for next graph replay
    }
  }
}

extern "C" void kernel_launch(void* const* d_in, const int* in_sizes, int n_in,
                              void* d_out, int out_size) {
  const float* x;
  const int* tgt32;
  if (in_sizes[0] == BB) {       // defensive input-order detection
    tgt32 = (const int*)d_in[0];
    x     = (const float*)d_in[1];
  } else {
    x     = (const float*)d_in[0];
    tgt32 = (const int*)d_in[1];
  }

  softmax_kernel<<<BB / 8, 256>>>(x, tgt32);
  dim3 gg(NBX, NCLS);
  gram_kernel<<<gg, 256>>>((float*)d_out);
}